// round 9
// baseline (speedup 1.0000x reference)
#include <cuda_runtime.h>
#include <cuda_bf16.h>
#include <cstdint>

#define NN 50000
#define EE 800000
#define ET (EE + NN)          // edges + self loops = 850000
#define HC 128                // H*C
#define HH 4
#define CC 32
#define NB 49                 // scan blocks: ceil(NN/1024)
#define LDS 136               // smem row stride (bf16 elems), padded

// ---------------- device scratch (static, no allocation) ----------------
__device__ float g_xp1[NN * HC];
__device__ float g_h1 [NN * HC];     // layer1 final (COMPACTED frontier rows)
__device__ float g_xp2[NN * HC];     // layer2 linear out (COMPACTED)
__device__ float g_as [NN * HH];
__device__ float g_ad [NN * HH];
__device__ int   g_cnt[NN];
__device__ int   g_rowptr[NN + 1];
__device__ int   g_srcs[ET];
__device__ int   g_mark[NN];
__device__ int   g_finv[NN];
__device__ int   g_flist[NN];
__device__ int   g_fcnt;
__device__ int   g_bsum[NB];
// pre-split/transposed weights: W^T stored [N=128][K] row-major, hi/lo
__device__ __align__(16) __nv_bfloat16 g_b1hi[128 * 256];
__device__ __align__(16) __nv_bfloat16 g_b1lo[128 * 256];
__device__ __align__(16) __nv_bfloat16 g_b2hi[128 * 128];
__device__ __align__(16) __nv_bfloat16 g_b2lo[128 * 128];

// ---------------- PTX helpers (baseline sm_80+ only: ldmatrix + mma.sync) ----
__device__ __forceinline__ uint32_t smem_u32(const void* p) {
    uint32_t a;
    asm("{ .reg .u64 t; cvta.to.shared.u64 t, %1; cvt.u32.u64 %0, t; }" : "=r"(a) : "l"(p));
    return a;
}
#define LDSM_X4(r, addr) \
    asm volatile("ldmatrix.sync.aligned.m8n8.x4.shared.b16 {%0,%1,%2,%3}, [%4];" \
                 : "=r"((r)[0]), "=r"((r)[1]), "=r"((r)[2]), "=r"((r)[3]) : "r"(addr))
#define MMA16816(c, a, b0, b1) \
    asm volatile("mma.sync.aligned.m16n8k16.row.col.f32.bf16.bf16.f32 " \
                 "{%0,%1,%2,%3}, {%4,%5,%6,%7}, {%8,%9}, {%0,%1,%2,%3};" \
                 : "+f"((c)[0]), "+f"((c)[1]), "+f"((c)[2]), "+f"((c)[3]) \
                 : "r"((a)[0]), "r"((a)[1]), "r"((a)[2]), "r"((a)[3]), "r"(b0), "r"(b1))

// ---------------- init / CSR build ----------------
__global__ void init_kernel() {
    int i = blockIdx.x * blockDim.x + threadIdx.x;
    if (i < NN) { g_cnt[i] = 0; g_mark[i] = 0; }
    if (i == 0) g_fcnt = 0;
}

__global__ void hist_kernel(const int* __restrict__ ei) {
    int e = blockIdx.x * blockDim.x + threadIdx.x;
    if (e >= ET) return;
    int d = (e < EE) ? ei[EE + e] : (e - EE);
    atomicAdd(&g_cnt[d], 1);
}

__global__ void scan1_kernel() {
    __shared__ int wsum[32];
    int tid = threadIdx.x, lane = tid & 31, w = tid >> 5;
    int i = blockIdx.x * 1024 + tid;
    int v = (i < NN) ? g_cnt[i] : 0;
    int x = v;
    #pragma unroll
    for (int o = 1; o < 32; o <<= 1) {
        int t = __shfl_up_sync(0xffffffffu, x, o);
        if (lane >= o) x += t;
    }
    if (lane == 31) wsum[w] = x;
    __syncthreads();
    if (w == 0) {
        int y = wsum[lane];
        #pragma unroll
        for (int o = 1; o < 32; o <<= 1) {
            int t = __shfl_up_sync(0xffffffffu, y, o);
            if (lane >= o) y += t;
        }
        wsum[lane] = y;
    }
    __syncthreads();
    int incl = x + (w > 0 ? wsum[w - 1] : 0);
    if (i < NN) g_rowptr[i + 1] = incl;
    if (tid == 1023) g_bsum[blockIdx.x] = incl;
    if (i == 0) g_rowptr[0] = 0;
}

__global__ void scan3_kernel() {
    __shared__ int s_off;
    int tid = threadIdx.x;
    if (tid < 32) {
        int v = 0;
        if (tid      < (int)blockIdx.x) v += g_bsum[tid];
        if (tid + 32 < (int)blockIdx.x) v += g_bsum[tid + 32];
        #pragma unroll
        for (int o = 16; o; o >>= 1) v += __shfl_xor_sync(0xffffffffu, v, o);
        if (tid == 0) s_off = v;
    }
    __syncthreads();
    int i = blockIdx.x * 1024 + tid;
    if (i < NN && blockIdx.x > 0) g_rowptr[i + 1] += s_off;
}

__global__ void scatter_kernel(const int* __restrict__ ei) {
    int e = blockIdx.x * blockDim.x + threadIdx.x;
    if (e >= ET) return;
    int s, d;
    if (e < EE) { s = ei[e]; d = ei[EE + e]; }
    else        { s = e - EE; d = s; }
    int r = atomicSub(&g_cnt[d], 1);
    g_srcs[g_rowptr[d] + r - 1] = s;
}

// ---------------- frontier ----------------
__global__ void mark_roots_kernel(const int* __restrict__ roots) {
    int r = roots[blockIdx.x];
    if (threadIdx.x == 0) g_mark[r] = 1;
    int beg = g_rowptr[r], end = g_rowptr[r + 1];
    for (int e = beg + threadIdx.x; e < end; e += 32)
        g_mark[g_srcs[e]] = 1;
}

__global__ void compact_kernel() {
    int i = blockIdx.x * blockDim.x + threadIdx.x;
    int lane = threadIdx.x & 31;
    bool active = (i < NN) && g_mark[i];
    unsigned mask = __ballot_sync(0xffffffffu, active);
    if (!mask) return;
    int leader = __ffs(mask) - 1;
    int base = 0;
    if (lane == leader) base = atomicAdd(&g_fcnt, __popc(mask));
    base = __shfl_sync(0xffffffffu, base, leader);
    if (active) {
        int pos = base + __popc(mask & ((1u << lane) - 1u));
        g_flist[pos] = i;
        g_finv[i] = pos;
    }
}

// ---------------- weight prep: W[K,128] -> W^T[N=128][K] hi/lo ----------------
__global__ void prep_w_kernel(const float* __restrict__ W,
                              __nv_bfloat16* __restrict__ hi, __nv_bfloat16* __restrict__ lo,
                              int K)
{
    int idx = blockIdx.x * blockDim.x + threadIdx.x;
    if (idx >= K * 128) return;
    int k = idx >> 7, n = idx & 127;
    float w = W[idx];
    __nv_bfloat16 h = __float2bfloat16(w);
    float r = w - __bfloat162float(h);
    hi[n * K + k] = h;
    lo[n * K + k] = __float2bfloat16(r);
}

// ---------------- tensor-core GEMM (mma.sync bf16, split hi/lo) + fused alpha --
// C[M,128] = A[M,KTOT] * W[KTOT,128].  8 warps: 4 row groups x 2 col groups.
// dyn smem: A_hi, A_lo, B_hi, B_lo tiles, each 128 x LDS bf16.
template <int KTOT, bool FRONT>
__global__ __launch_bounds__(256) void gemm_mma_kernel(
    const float* __restrict__ A,
    const __nv_bfloat16* __restrict__ Bhi, const __nv_bfloat16* __restrict__ Blo,
    const float* __restrict__ a_src, const float* __restrict__ a_dst,
    float* __restrict__ Cmat, float* __restrict__ as_out, float* __restrict__ ad_out)
{
    constexpr int CHUNKS = KTOT / 128;
    int M = FRONT ? g_fcnt : NN;
    int row0 = blockIdx.x * 128;
    if (row0 >= M) return;

    extern __shared__ __nv_bfloat16 sm[];
    __nv_bfloat16* AHI = sm;
    __nv_bfloat16* ALO = sm + 128 * LDS;
    __nv_bfloat16* BHI = sm + 2 * 128 * LDS;
    __nv_bfloat16* BLO = sm + 3 * 128 * LDS;

    int tid = threadIdx.x, wid = tid >> 5, lane = tid & 31;
    int rm = wid & 3;          // row group: rows rm*32 .. +31
    int cn = wid >> 2;         // col group: cols cn*64 .. +63

    float c[2][8][4];
    #pragma unroll
    for (int i = 0; i < 2; i++)
        #pragma unroll
        for (int j = 0; j < 8; j++)
            #pragma unroll
            for (int k = 0; k < 4; k++) c[i][j][k] = 0.f;

    int lrow = lane & 15, lseg = (lane >> 4) << 3;

    #pragma unroll
    for (int ch = 0; ch < CHUNKS; ch++) {
        if (ch) __syncthreads();
        // ---- convert A chunk fp32 -> bf16 hi/lo into smem
        for (int p = tid; p < 128 * 64; p += 256) {
            int row = p >> 6, cp = (p & 63) * 2;
            int gr = row0 + row;
            float2 v = make_float2(0.f, 0.f);
            if (gr < M) v = *(const float2*)&A[(long)gr * KTOT + ch * 128 + cp];
            __nv_bfloat16 h0 = __float2bfloat16(v.x), h1 = __float2bfloat16(v.y);
            float r0 = v.x - __bfloat162float(h0);
            float r1 = v.y - __bfloat162float(h1);
            __nv_bfloat16 l0 = __float2bfloat16(r0), l1 = __float2bfloat16(r1);
            *(uint32_t*)&AHI[row * LDS + cp] =
                (uint32_t)__bfloat16_as_ushort(h0) | ((uint32_t)__bfloat16_as_ushort(h1) << 16);
            *(uint32_t*)&ALO[row * LDS + cp] =
                (uint32_t)__bfloat16_as_ushort(l0) | ((uint32_t)__bfloat16_as_ushort(l1) << 16);
        }
        // ---- copy B chunk (W^T rows, 128 x 128 bf16) into smem
        for (int i = tid; i < 128 * 16; i += 256) {
            int row = i >> 4, seg = (i & 15) * 8;
            *(uint4*)&BHI[row * LDS + seg] = *(const uint4*)&Bhi[(long)row * KTOT + ch * 128 + seg];
            *(uint4*)&BLO[row * LDS + seg] = *(const uint4*)&Blo[(long)row * KTOT + ch * 128 + seg];
        }
        __syncthreads();

        #pragma unroll
        for (int ks = 0; ks < 8; ks++) {
            int k0 = ks * 16;
            uint32_t ah[2][4], al[2][4];
            #pragma unroll
            for (int ma = 0; ma < 2; ma++) {
                int r0 = rm * 32 + ma * 16;
                LDSM_X4(ah[ma], smem_u32(&AHI[(r0 + lrow) * LDS + k0 + lseg]));
                LDSM_X4(al[ma], smem_u32(&ALO[(r0 + lrow) * LDS + k0 + lseg]));
            }
            #pragma unroll
            for (int nb = 0; nb < 4; nb++) {
                int n0 = cn * 64 + nb * 16;
                uint32_t bh[4], bl[4];
                LDSM_X4(bh, smem_u32(&BHI[(n0 + lrow) * LDS + k0 + lseg]));
                LDSM_X4(bl, smem_u32(&BLO[(n0 + lrow) * LDS + k0 + lseg]));
                #pragma unroll
                for (int ma = 0; ma < 2; ma++) {
                    MMA16816(c[ma][nb * 2],     ah[ma], bh[0], bh[2]);
                    MMA16816(c[ma][nb * 2],     ah[ma], bl[0], bl[2]);
                    MMA16816(c[ma][nb * 2],     al[ma], bh[0], bh[2]);
                    MMA16816(c[ma][nb * 2 + 1], ah[ma], bh[1], bh[3]);
                    MMA16816(c[ma][nb * 2 + 1], ah[ma], bl[1], bl[3]);
                    MMA16816(c[ma][nb * 2 + 1], al[ma], bh[1], bh[3]);
                }
            }
        }
    }

    // ---- epilogue: write C + fused alpha dots
    int q = lane >> 2, qq = lane & 3;
    float av[16], dv[16];
    #pragma unroll
    for (int na = 0; na < 8; na++) {
        int col = cn * 64 + na * 8 + qq * 2;
        av[na * 2]     = a_src[col];
        av[na * 2 + 1] = a_src[col + 1];
        dv[na * 2]     = a_dst[col];
        dv[na * 2 + 1] = a_dst[col + 1];
    }

    #pragma unroll
    for (int ma = 0; ma < 2; ma++) {
        #pragma unroll
        for (int half = 0; half < 2; half++) {
            int r = row0 + rm * 32 + ma * 16 + q + half * 8;
            bool valid = r < M;
            float s1a = 0.f, s1b = 0.f, s2a = 0.f, s2b = 0.f;
            #pragma unroll
            for (int na = 0; na < 8; na++) {
                float v0 = c[ma][na][half * 2];
                float v1 = c[ma][na][half * 2 + 1];
                if (valid) {
                    int col = cn * 64 + na * 8 + qq * 2;
                    *(float2*)&Cmat[(long)r * HC + col] = make_float2(v0, v1);
                }
                float ps = v0 * av[na * 2] + v1 * av[na * 2 + 1];
                float pd = v0 * dv[na * 2] + v1 * dv[na * 2 + 1];
                if (na < 4) { s1a += ps; s2a += pd; }
                else        { s1b += ps; s2b += pd; }
            }
            s1a += __shfl_xor_sync(0xffffffffu, s1a, 1);
            s1a += __shfl_xor_sync(0xffffffffu, s1a, 2);
            s1b += __shfl_xor_sync(0xffffffffu, s1b, 1);
            s1b += __shfl_xor_sync(0xffffffffu, s1b, 2);
            s2a += __shfl_xor_sync(0xffffffffu, s2a, 1);
            s2a += __shfl_xor_sync(0xffffffffu, s2a, 2);
            s2b += __shfl_xor_sync(0xffffffffu, s2b, 1);
            s2b += __shfl_xor_sync(0xffffffffu, s2b, 2);
            if (valid && qq == 0) {
                as_out[r * HH + cn * 2]     = s1a;
                as_out[r * HH + cn * 2 + 1] = s1b;
                ad_out[r * HH + cn * 2]     = s2a;
                ad_out[r * HH + cn * 2 + 1] = s2b;
            }
        }
    }
}

// ---------------- two-pass softmax aggregation core ----------------
__device__ __forceinline__ void aggregate_node(
    const float* __restrict__ xp, const float* __restrict__ as_in, float adv,
    int beg, int end, int h, int lane, const int* __restrict__ remap,
    float& accO, float& lO)
{
    __shared__ float sp[HH][32];
    __shared__ int   ss[HH][32];

    float m = -1e30f;
    for (int e = beg + lane; e < end; e += 32) {
        int s = g_srcs[e];
        int fs = remap ? remap[s] : s;
        float lg = as_in[fs * HH + h] + adv;
        lg = lg > 0.f ? lg : 0.2f * lg;
        m = fmaxf(m, lg);
    }
    #pragma unroll
    for (int o = 16; o; o >>= 1) m = fmaxf(m, __shfl_xor_sync(0xffffffffu, m, o));

    float l = 0.f, acc = 0.f;
    for (int base = beg; base < end; base += 32) {
        int e = base + lane;
        int s = 0;
        float p = 0.f;
        if (e < end) {
            s = g_srcs[e];
            if (remap) s = remap[s];
            float lg = as_in[s * HH + h] + adv;
            lg = lg > 0.f ? lg : 0.2f * lg;
            p = __expf(lg - m);
        }
        l += p;
        sp[h][lane] = p;
        ss[h][lane] = s;
        __syncwarp();
        int cnt = min(32, end - base);
        #pragma unroll 4
        for (int i = 0; i < cnt; i++) {
            acc += sp[h][i] * xp[(long)ss[h][i] * HC + h * CC + lane];
        }
        __syncwarp();
    }
    #pragma unroll
    for (int o = 16; o; o >>= 1) l += __shfl_xor_sync(0xffffffffu, l, o);
    accO = acc; lO = l;
}

__global__ void aggregate1_kernel(const float* __restrict__ xp,
                                  const float* __restrict__ as_in,
                                  const float* __restrict__ ad_in,
                                  const float* __restrict__ bias,
                                  float* __restrict__ out)
{
    int bi = blockIdx.x;
    if (bi >= g_fcnt) return;
    int node = g_flist[bi];
    int tid  = threadIdx.x;
    int h = tid >> 5, lane = tid & 31;

    int beg = g_rowptr[node];
    int end = g_rowptr[node + 1];
    float adv = ad_in[node * HH + h];

    float acc, l;
    aggregate_node(xp, as_in, adv, beg, end, h, lane, nullptr, acc, l);
    float o = acc / (l + 1e-16f) + bias[h * CC + lane];
    out[(long)bi * HC + tid] = fmaxf(o, 0.f);
}

__global__ void aggregate2_kernel(const float* __restrict__ xpc,
                                  const float* __restrict__ as_c,
                                  const float* __restrict__ ad_c,
                                  const float* __restrict__ bias,
                                  float* __restrict__ out,
                                  const int* __restrict__ roots)
{
    int bi   = blockIdx.x;
    int node = roots[bi];
    int tid  = threadIdx.x;
    int h = tid >> 5, lane = tid & 31;

    int beg = g_rowptr[node];
    int end = g_rowptr[node + 1];
    float adv = ad_c[g_finv[node] * HH + h];

    float acc, l;
    aggregate_node(xpc, as_c, adv, beg, end, h, lane, g_finv, acc, l);
    out[(long)bi * HC + tid] = acc / (l + 1e-16f) + bias[h * CC + lane];
}

// ---------------- launch ----------------
extern "C" void kernel_launch(void* const* d_in, const int* in_sizes, int n_in,
                              void* d_out, int out_size)
{
    const float* x    = (const float*)d_in[0];
    const int*   ei   = (const int*)  d_in[1];
    const int*   root = (const int*)  d_in[2];
    const float* W1   = (const float*)d_in[3];
    const float* as1  = (const float*)d_in[4];
    const float* ad1  = (const float*)d_in[5];
    const float* b1   = (const float*)d_in[6];
    const float* W2   = (const float*)d_in[7];
    const float* as2  = (const float*)d_in[8];
    const float* ad2  = (const float*)d_in[9];
    const float* b2   = (const float*)d_in[10];
    float* out = (float*)d_out;
    int n_roots = in_sizes[2];

    float *d_xp1, *d_h1, *d_xp2, *d_as, *d_ad;
    __nv_bfloat16 *d_b1hi, *d_b1lo, *d_b2hi, *d_b2lo;
    cudaGetSymbolAddress((void**)&d_xp1, g_xp1);
    cudaGetSymbolAddress((void**)&d_h1,  g_h1);
    cudaGetSymbolAddress((void**)&d_xp2, g_xp2);
    cudaGetSymbolAddress((void**)&d_as,  g_as);
    cudaGetSymbolAddress((void**)&d_ad,  g_ad);
    cudaGetSymbolAddress((void**)&d_b1hi, g_b1hi);
    cudaGetSymbolAddress((void**)&d_b1lo, g_b1lo);
    cudaGetSymbolAddress((void**)&d_b2hi, g_b2hi);
    cudaGetSymbolAddress((void**)&d_b2lo, g_b2lo);

    const int SMEM_SZ = 4 * 128 * LDS * (int)sizeof(__nv_bfloat16);   // 139264 B
    cudaFuncSetAttribute(gemm_mma_kernel<256, false>,
                         cudaFuncAttributeMaxDynamicSharedMemorySize, SMEM_SZ);
    cudaFuncSetAttribute(gemm_mma_kernel<128, true>,
                         cudaFuncAttributeMaxDynamicSharedMemorySize, SMEM_SZ);

    // ---- weight prep ----
    prep_w_kernel<<<(256 * 128 + 255) / 256, 256>>>(W1, d_b1hi, d_b1lo, 256);
    prep_w_kernel<<<(128 * 128 + 255) / 256, 256>>>(W2, d_b2hi, d_b2lo, 128);

    // ---- build CSR (dst-sorted) ----
    init_kernel<<<NB, 1024>>>();
    hist_kernel<<<(ET + 511) / 512, 512>>>(ei);
    scan1_kernel<<<NB, 1024>>>();
    scan3_kernel<<<NB, 1024>>>();
    scatter_kernel<<<(ET + 511) / 512, 512>>>(ei);

    // ---- frontier = roots + their in-edge sources ----
    mark_roots_kernel<<<n_roots, 32>>>(root);
    compact_kernel<<<(NN + 255) / 256, 256>>>();

    // ---- layer 1 ----
    gemm_mma_kernel<256, false><<<(NN + 127) / 128, 256, SMEM_SZ>>>(
        x, d_b1hi, d_b1lo, as1, ad1, d_xp1, d_as, d_ad);
    aggregate1_kernel<<<NN, 128>>>(d_xp1, d_as, d_ad, b1, d_h1);

    // ---- layer 2 (dense over compacted frontier rows) ----
    gemm_mma_kernel<128, true><<<(NN + 127) / 128, 256, SMEM_SZ>>>(
        d_h1, d_b2hi, d_b2lo, as2, ad2, d_xp2, d_as, d_ad);
    aggregate2_kernel<<<n_roots, 128>>>(d_xp2, d_as, d_ad, b2, out, root);
}

// round 11
// speedup vs baseline: 1.3412x; 1.3412x over previous
#include <cuda_runtime.h>
#include <cuda_bf16.h>

#define NN 50000
#define EE 800000
#define ET (EE + NN)          // edges + self loops = 850000
#define HC 128                // H*C
#define HH 4
#define CC 32
#define NB 49                 // scan blocks: ceil(NN/1024)

// ---------------- device scratch (static, no allocation) ----------------
__device__ float g_xp1[NN * HC];     // layer1 linear out (full)
__device__ float g_h1 [NN * HC];     // layer1 final (COMPACTED frontier rows)
__device__ float g_xp2[NN * HC];     // layer2 linear out (COMPACTED)
__device__ float g_as [NN * HH];
__device__ float g_ad [NN * HH];
__device__ int   g_cnt[NN];          // degree histogram / scatter countdown
__device__ int   g_rowptr[NN + 1];
__device__ int   g_srcs[ET];         // CSR (by dst) source indices
__device__ int   g_mark[NN];
__device__ int   g_finv[NN];         // node -> compact frontier index
__device__ int   g_flist[NN];        // compact frontier index -> node
__device__ int   g_fcnt;
__device__ int   g_bsum[NB];

// ---------------- f32x2 helpers ----------------
#define FMA2(acc, a, b) asm("fma.rn.f32x2 %0, %1, %2, %0;" : "+l"(acc) : "l"(a), "l"(b))
#define SPLAT2(dst, s)  asm("mov.b64 %0, {%1, %1};" : "=l"(dst) : "r"(__float_as_uint(s)))
#define UNPACK2(lo, hi, p) asm("mov.b64 {%0, %1}, %2;" : "=r"(lo), "=r"(hi) : "l"(p))

// ---------------- init: zero cnt/mark/fcnt ----------------
__global__ void init_kernel() {
    int i = blockIdx.x * blockDim.x + threadIdx.x;
    if (i < NN) { g_cnt[i] = 0; g_mark[i] = 0; }
    if (i == 0) g_fcnt = 0;
}

__global__ void hist_kernel(const int* __restrict__ ei) {
    int e = blockIdx.x * blockDim.x + threadIdx.x;
    if (e >= ET) return;
    int d = (e < EE) ? ei[EE + e] : (e - EE);
    atomicAdd(&g_cnt[d], 1);
}

// ---------------- 2-phase scan (block offsets recomputed in phase 2) --------
__global__ void scan1_kernel() {
    __shared__ int wsum[32];
    int tid = threadIdx.x, lane = tid & 31, w = tid >> 5;
    int i = blockIdx.x * 1024 + tid;
    int v = (i < NN) ? g_cnt[i] : 0;
    int x = v;
    #pragma unroll
    for (int o = 1; o < 32; o <<= 1) {
        int t = __shfl_up_sync(0xffffffffu, x, o);
        if (lane >= o) x += t;
    }
    if (lane == 31) wsum[w] = x;
    __syncthreads();
    if (w == 0) {
        int y = wsum[lane];
        #pragma unroll
        for (int o = 1; o < 32; o <<= 1) {
            int t = __shfl_up_sync(0xffffffffu, y, o);
            if (lane >= o) y += t;
        }
        wsum[lane] = y;
    }
    __syncthreads();
    int incl = x + (w > 0 ? wsum[w - 1] : 0);
    if (i < NN) g_rowptr[i + 1] = incl;
    if (tid == 1023) g_bsum[blockIdx.x] = incl;
    if (i == 0) g_rowptr[0] = 0;
}

__global__ void scan3_kernel() {
    __shared__ int s_off;
    int tid = threadIdx.x;
    if (tid < 32) {
        int v = 0;
        if (tid      < (int)blockIdx.x) v += g_bsum[tid];
        if (tid + 32 < (int)blockIdx.x) v += g_bsum[tid + 32];
        #pragma unroll
        for (int o = 16; o; o >>= 1) v += __shfl_xor_sync(0xffffffffu, v, o);
        if (tid == 0) s_off = v;
    }
    __syncthreads();
    int i = blockIdx.x * 1024 + tid;
    if (i < NN && blockIdx.x > 0) g_rowptr[i + 1] += s_off;
}

// scatter with countdown (no second zero pass)
__global__ void scatter_kernel(const int* __restrict__ ei) {
    int e = blockIdx.x * blockDim.x + threadIdx.x;
    if (e >= ET) return;
    int s, d;
    if (e < EE) { s = ei[e]; d = ei[EE + e]; }
    else        { s = e - EE; d = s; }
    int r = atomicSub(&g_cnt[d], 1);
    g_srcs[g_rowptr[d] + r - 1] = s;
}

// ---------------- frontier: roots + sources of in-edges of roots ----------------
__global__ void mark_roots_kernel(const int* __restrict__ roots) {
    int r = roots[blockIdx.x];
    if (threadIdx.x == 0) g_mark[r] = 1;
    int beg = g_rowptr[r], end = g_rowptr[r + 1];
    for (int e = beg + threadIdx.x; e < end; e += 32)
        g_mark[g_srcs[e]] = 1;
}

__global__ void compact_kernel() {
    int i = blockIdx.x * blockDim.x + threadIdx.x;
    int lane = threadIdx.x & 31;
    bool active = (i < NN) && g_mark[i];
    unsigned mask = __ballot_sync(0xffffffffu, active);
    if (!mask) return;
    int leader = __ffs(mask) - 1;
    int base = 0;
    if (lane == leader) base = atomicAdd(&g_fcnt, __popc(mask));
    base = __shfl_sync(0xffffffffu, base, leader);
    if (active) {
        int pos = base + __popc(mask & ((1u << lane) - 1u));
        g_flist[pos] = i;
        g_finv[i] = pos;
    }
}

// ---------------- fused GEMM + alpha, double-buffered smem ----------------
// C[M,128] = A[M,K] * B[K,128]; epilogue produces as/ad = <row_h, att_h>.
template <int K, bool FRONT>
__global__ __launch_bounds__(256) void gemm_alpha_kernel(
    const float* __restrict__ A, const float* __restrict__ B, float* __restrict__ Cmat,
    const float* __restrict__ a_src, const float* __restrict__ a_dst,
    float* __restrict__ as_out, float* __restrict__ ad_out)
{
    constexpr int NC = K / 16;
    int M = FRONT ? g_fcnt : NN;
    int row0 = blockIdx.x * 128;
    if (row0 >= M) return;

    __shared__ __align__(16) float As[2][16][128];
    __shared__ __align__(16) float Bs[2][16][128];
    int tid = threadIdx.x;
    int tx = tid & 15;       // col group: cols tx*8..tx*8+7
    int ty = tid >> 4;       // row group: rows ty*8..ty*8+7

    unsigned long long acc2[8][4];
    #pragma unroll
    for (int i = 0; i < 8; i++)
        #pragma unroll
        for (int j = 0; j < 4; j++) acc2[i][j] = 0ULL;

    int lr = tid >> 1;           // 0..127 row for A load
    int lk = (tid & 1) * 8;      // 0 or 8
    int bk = tid >> 4;           // 0..15 k-row for B load
    int bn = (tid & 15) * 8;     // col

    int grow = row0 + lr;
    bool arow_ok = grow < M;
    const float* Arow = A + (long)grow * K + lk;
    const float* Bp   = B + bk * 128 + bn;

    float4 pa0, pa1, pb0, pb1;
    if (arow_ok) {
        pa0 = *(const float4*)(Arow);
        pa1 = *(const float4*)(Arow + 4);
    } else {
        pa0 = make_float4(0, 0, 0, 0); pa1 = pa0;
    }
    pb0 = *(const float4*)(Bp);
    pb1 = *(const float4*)(Bp + 4);
    {
        As[0][lk + 0][lr] = pa0.x; As[0][lk + 1][lr] = pa0.y;
        As[0][lk + 2][lr] = pa0.z; As[0][lk + 3][lr] = pa0.w;
        As[0][lk + 4][lr] = pa1.x; As[0][lk + 5][lr] = pa1.y;
        As[0][lk + 6][lr] = pa1.z; As[0][lk + 7][lr] = pa1.w;
        *(float4*)&Bs[0][bk][bn]     = pb0;
        *(float4*)&Bs[0][bk][bn + 4] = pb1;
    }
    __syncthreads();

    int buf = 0;
    #pragma unroll
    for (int c = 0; c < NC; c++) {
        if (c + 1 < NC) {
            if (arow_ok) {
                pa0 = *(const float4*)(Arow + (c + 1) * 16);
                pa1 = *(const float4*)(Arow + (c + 1) * 16 + 4);
            }
            pb0 = *(const float4*)(Bp + (c + 1) * 16 * 128);
            pb1 = *(const float4*)(Bp + (c + 1) * 16 * 128 + 4);
        }

        #pragma unroll
        for (int k = 0; k < 16; k++) {
            float4 a0 = *(const float4*)&As[buf][k][ty * 8];
            float4 a1 = *(const float4*)&As[buf][k][ty * 8 + 4];
            ulonglong2 bl = *(const ulonglong2*)&Bs[buf][k][tx * 8];
            ulonglong2 bh = *(const ulonglong2*)&Bs[buf][k][tx * 8 + 4];
            unsigned long long br2[4] = {bl.x, bl.y, bh.x, bh.y};
            float ar[8] = {a0.x, a0.y, a0.z, a0.w, a1.x, a1.y, a1.z, a1.w};
            unsigned long long ap[8];
            #pragma unroll
            for (int i = 0; i < 8; i++) SPLAT2(ap[i], ar[i]);
            #pragma unroll
            for (int i = 0; i < 8; i++)
                #pragma unroll
                for (int j = 0; j < 4; j++)
                    FMA2(acc2[i][j], ap[i], br2[j]);
        }

        if (c + 1 < NC) {
            int nb = buf ^ 1;
            As[nb][lk + 0][lr] = pa0.x; As[nb][lk + 1][lr] = pa0.y;
            As[nb][lk + 2][lr] = pa0.z; As[nb][lk + 3][lr] = pa0.w;
            As[nb][lk + 4][lr] = pa1.x; As[nb][lk + 5][lr] = pa1.y;
            As[nb][lk + 6][lr] = pa1.z; As[nb][lk + 7][lr] = pa1.w;
            *(float4*)&Bs[nb][bk][bn]     = pb0;
            *(float4*)&Bs[nb][bk][bn + 4] = pb1;
            __syncthreads();
            buf = nb;
        }
    }

    // attention vectors for this thread's 8-col chunk (within head h = tx>>2)
    float4 av0 = *(const float4*)&a_src[tx * 8];
    float4 av1 = *(const float4*)&a_src[tx * 8 + 4];
    float4 dv0 = *(const float4*)&a_dst[tx * 8];
    float4 dv1 = *(const float4*)&a_dst[tx * 8 + 4];
    int lane = tid & 31;
    int h = tx >> 2;

    #pragma unroll
    for (int i = 0; i < 8; i++) {
        float c[8];
        #pragma unroll
        for (int j = 0; j < 4; j++) {
            unsigned int lo, hi;
            UNPACK2(lo, hi, acc2[i][j]);
            c[2 * j]     = __uint_as_float(lo);
            c[2 * j + 1] = __uint_as_float(hi);
        }
        int gr = row0 + ty * 8 + i;
        bool valid = gr < M;
        if (valid) {
            *(float4*)&Cmat[(long)gr * 128 + tx * 8]     = make_float4(c[0], c[1], c[2], c[3]);
            *(float4*)&Cmat[(long)gr * 128 + tx * 8 + 4] = make_float4(c[4], c[5], c[6], c[7]);
        }
        float s1 = c[0]*av0.x + c[1]*av0.y + c[2]*av0.z + c[3]*av0.w
                 + c[4]*av1.x + c[5]*av1.y + c[6]*av1.z + c[7]*av1.w;
        float s2 = c[0]*dv0.x + c[1]*dv0.y + c[2]*dv0.z + c[3]*dv0.w
                 + c[4]*dv1.x + c[5]*dv1.y + c[6]*dv1.z + c[7]*dv1.w;
        s1 += __shfl_xor_sync(0xffffffffu, s1, 1);
        s1 += __shfl_xor_sync(0xffffffffu, s1, 2);
        s2 += __shfl_xor_sync(0xffffffffu, s2, 1);
        s2 += __shfl_xor_sync(0xffffffffu, s2, 2);
        if (valid && (lane & 3) == 0) {
            as_out[gr * HH + h] = s1;
            ad_out[gr * HH + h] = s2;
        }
    }
}

// ---------------- two-pass softmax aggregation core ----------------
__device__ __forceinline__ void aggregate_node(
    const float* __restrict__ xp, const float* __restrict__ as_in, float adv,
    int beg, int end, int h, int lane, const int* __restrict__ remap,
    float& accO, float& lO)
{
    __shared__ float sp[HH][32];
    __shared__ int   ss[HH][32];

    float m = -1e30f;
    for (int e = beg + lane; e < end; e += 32) {
        int s = g_srcs[e];
        int fs = remap ? remap[s] : s;
        float lg = as_in[fs * HH + h] + adv;
        lg = lg > 0.f ? lg : 0.2f * lg;
        m = fmaxf(m, lg);
    }
    #pragma unroll
    for (int o = 16; o; o >>= 1) m = fmaxf(m, __shfl_xor_sync(0xffffffffu, m, o));

    float l = 0.f, acc = 0.f;
    for (int base = beg; base < end; base += 32) {
        int e = base + lane;
        int s = 0;
        float p = 0.f;
        if (e < end) {
            s = g_srcs[e];
            if (remap) s = remap[s];
            float lg = as_in[s * HH + h] + adv;
            lg = lg > 0.f ? lg : 0.2f * lg;
            p = __expf(lg - m);
        }
        l += p;
        sp[h][lane] = p;
        ss[h][lane] = s;
        __syncwarp();
        int cnt = min(32, end - base);
        #pragma unroll 4
        for (int i = 0; i < cnt; i++) {
            acc += sp[h][i] * xp[(long)ss[h][i] * HC + h * CC + lane];
        }
        __syncwarp();
    }
    #pragma unroll
    for (int o = 16; o; o >>= 1) l += __shfl_xor_sync(0xffffffffu, l, o);
    accO = acc; lO = l;
}

// grid-stride over frontier nodes
__global__ void aggregate1_kernel(const float* __restrict__ xp,
                                  const float* __restrict__ as_in,
                                  const float* __restrict__ ad_in,
                                  const float* __restrict__ bias,
                                  float* __restrict__ out)
{
    int tid  = threadIdx.x;
    int h = tid >> 5, lane = tid & 31;
    for (int bi = blockIdx.x; bi < g_fcnt; bi += gridDim.x) {
        int node = g_flist[bi];
        int beg = g_rowptr[node];
        int end = g_rowptr[node + 1];
        float adv = ad_in[node * HH + h];

        float acc, l;
        aggregate_node(xp, as_in, adv, beg, end, h, lane, nullptr, acc, l);
        float o = acc / (l + 1e-16f) + bias[h * CC + lane];
        out[(long)bi * HC + tid] = fmaxf(o, 0.f);   // relu
        __syncthreads();
    }
}

__global__ void aggregate2_kernel(const float* __restrict__ xpc,
                                  const float* __restrict__ as_c,
                                  const float* __restrict__ ad_c,
                                  const float* __restrict__ bias,
                                  float* __restrict__ out,
                                  const int* __restrict__ roots)
{
    int bi   = blockIdx.x;
    int node = roots[bi];
    int tid  = threadIdx.x;
    int h = tid >> 5, lane = tid & 31;

    int beg = g_rowptr[node];
    int end = g_rowptr[node + 1];
    float adv = ad_c[g_finv[node] * HH + h];

    float acc, l;
    aggregate_node(xpc, as_c, adv, beg, end, h, lane, g_finv, acc, l);
    out[(long)bi * HC + tid] = acc / (l + 1e-16f) + bias[h * CC + lane];
}

// ---------------- launch ----------------
extern "C" void kernel_launch(void* const* d_in, const int* in_sizes, int n_in,
                              void* d_out, int out_size)
{
    const float* x    = (const float*)d_in[0];
    const int*   ei   = (const int*)  d_in[1];
    const int*   root = (const int*)  d_in[2];
    const float* W1   = (const float*)d_in[3];
    const float* as1  = (const float*)d_in[4];
    const float* ad1  = (const float*)d_in[5];
    const float* b1   = (const float*)d_in[6];
    const float* W2   = (const float*)d_in[7];
    const float* as2  = (const float*)d_in[8];
    const float* ad2  = (const float*)d_in[9];
    const float* b2   = (const float*)d_in[10];
    float* out = (float*)d_out;
    int n_roots = in_sizes[2];

    float *d_xp1, *d_h1, *d_xp2, *d_as, *d_ad;
    cudaGetSymbolAddress((void**)&d_xp1, g_xp1);
    cudaGetSymbolAddress((void**)&d_h1,  g_h1);
    cudaGetSymbolAddress((void**)&d_xp2, g_xp2);
    cudaGetSymbolAddress((void**)&d_as,  g_as);
    cudaGetSymbolAddress((void**)&d_ad,  g_ad);

    // side stream + events, created once on the first (uncaptured) call
    static cudaStream_t s2 = nullptr;
    static cudaEvent_t evFork = nullptr, evJoin = nullptr;
    if (!s2) {
        cudaStreamCreateWithFlags(&s2, cudaStreamNonBlocking);
        cudaEventCreateWithFlags(&evFork, cudaEventDisableTiming);
        cudaEventCreateWithFlags(&evJoin, cudaEventDisableTiming);
    }

    // ---- fork: CSR build + frontier on s2, concurrent with GEMM1 on stream 0
    cudaEventRecord(evFork, 0);
    cudaStreamWaitEvent(s2, evFork, 0);

    init_kernel<<<NB, 1024, 0, s2>>>();
    hist_kernel<<<(ET + 511) / 512, 512, 0, s2>>>(ei);
    scan1_kernel<<<NB, 1024, 0, s2>>>();
    scan3_kernel<<<NB, 1024, 0, s2>>>();
    scatter_kernel<<<(ET + 511) / 512, 512, 0, s2>>>(ei);
    mark_roots_kernel<<<n_roots, 32, 0, s2>>>(root);
    compact_kernel<<<(NN + 255) / 256, 256, 0, s2>>>();
    cudaEventRecord(evJoin, s2);

    // ---- stream 0: layer-1 GEMM (+fused alpha), independent of CSR
    gemm_alpha_kernel<256, false><<<(NN + 127) / 128, 256>>>(x, W1, d_xp1, as1, ad1, d_as, d_ad);

    // ---- join, then aggregation / layer 2
    cudaStreamWaitEvent(0, evJoin, 0);
    aggregate1_kernel<<<24576, 128>>>(d_xp1, d_as, d_ad, b1, d_h1);

    gemm_alpha_kernel<128, true><<<(NN + 127) / 128, 256>>>(d_h1, W2, d_xp2, as2, ad2, d_as, d_ad);
    aggregate2_kernel<<<n_roots, 128>>>(d_xp2, d_as, d_ad, b2, out, root);
}